// round 1
// baseline (speedup 1.0000x reference)
#include <cuda_runtime.h>
#include <cstdint>

#define BB 4
#define AA 9
#define HH 50
#define WW 76
#define NN (AA * HH * WW)          // 34200 boxes per image
#define PRE 4000
#define POST 300
#define SORTN 4096
#define NMS_THR 0.7f

// ---------------- static scratch (no allocation allowed) ----------------
__device__ float4   d_props[BB * NN];      // decoded clipped boxes
__device__ unsigned d_keys [BB * NN];      // flipped-float sortable score keys
__device__ float4   d_sorted[BB * PRE];    // top-4000 boxes, score-desc order

// ---------------- helpers ----------------
__device__ __forceinline__ float areaf(float4 b) {
    return __fmul_rn(__fsub_rn(b.z, b.x), __fsub_rn(b.w, b.y));
}

__device__ __forceinline__ bool iou_gt(float4 a, float aA, float4 b, float aB) {
    float xx1 = fmaxf(a.x, b.x);
    float yy1 = fmaxf(a.y, b.y);
    float xx2 = fminf(a.z, b.z);
    float yy2 = fminf(a.w, b.w);
    float w = fmaxf(__fsub_rn(xx2, xx1), 0.0f);
    float h = fmaxf(__fsub_rn(yy2, yy1), 0.0f);
    float inter = __fmul_rn(w, h);
    float denom = __fadd_rn(__fsub_rn(__fadd_rn(aA, aB), inter), 1e-9f);
    return __fdiv_rn(inter, denom) > NMS_THR;
}

// ---------------- 1) decode + key + output prefill ----------------
__global__ void decode_kernel(const float* __restrict__ scores,
                              const float* __restrict__ deltas,
                              const float* __restrict__ im_info,
                              const float* __restrict__ anchors,
                              float* __restrict__ out) {
    int t = blockIdx.x * blockDim.x + threadIdx.x;

    // prefill out rows to [b, 0, 0, 0, 0]
    if (t < BB * POST * 5) {
        int col = t % 5;
        int b = t / (POST * 5);
        out[t] = (col == 0) ? (float)b : 0.0f;
    }
    if (t >= BB * NN) return;

    int b = t / NN;
    int i = t - b * NN;
    int a = i % AA;
    int p = i / AA;
    int x = p % WW;
    int y = p / WW;

    float sx = (float)(x * 16);
    float sy = (float)(y * 16);
    float ax1 = __fadd_rn(anchors[a * 4 + 0], sx);
    float ay1 = __fadd_rn(anchors[a * 4 + 1], sy);
    float ax2 = __fadd_rn(anchors[a * 4 + 2], sx);
    float ay2 = __fadd_rn(anchors[a * 4 + 3], sy);

    float w  = __fadd_rn(__fsub_rn(ax2, ax1), 1.0f);
    float h  = __fadd_rn(__fsub_rn(ay2, ay1), 1.0f);
    float cx = __fadd_rn(ax1, __fmul_rn(0.5f, w));
    float cy = __fadd_rn(ay1, __fmul_rn(0.5f, h));

    const int HW = HH * WW;
    size_t dbase = ((size_t)b * 4 * AA + a * 4) * HW + (size_t)y * WW + x;
    float dx  = deltas[dbase];
    float dy  = deltas[dbase + HW];
    float dz  = deltas[dbase + 2 * HW];
    float dw_ = deltas[dbase + 3 * HW];

    float pcx = __fadd_rn(__fmul_rn(dx, w), cx);
    float pcy = __fadd_rn(__fmul_rn(dy, h), cy);
    float pw  = __fmul_rn(expf(dz),  w);
    float ph  = __fmul_rn(expf(dw_), h);

    float x1 = __fsub_rn(pcx, __fmul_rn(0.5f, pw));
    float y1 = __fsub_rn(pcy, __fmul_rn(0.5f, ph));
    float x2 = __fadd_rn(pcx, __fmul_rn(0.5f, pw));
    float y2 = __fadd_rn(pcy, __fmul_rn(0.5f, ph));

    float hiw = __fsub_rn(im_info[b * 3 + 1], 1.0f);
    float hih = __fsub_rn(im_info[b * 3 + 0], 1.0f);
    x1 = fminf(fmaxf(x1, 0.0f), hiw);
    y1 = fminf(fmaxf(y1, 0.0f), hih);
    x2 = fminf(fmaxf(x2, 0.0f), hiw);
    y2 = fminf(fmaxf(y2, 0.0f), hih);

    d_props[t] = make_float4(x1, y1, x2, y2);

    float s = scores[((size_t)b * AA + a) * HW + (size_t)y * WW + x];
    unsigned bits = __float_as_uint(s);
    d_keys[t] = (bits & 0x80000000u) ? ~bits : (bits | 0x80000000u);
}

// ---------------- 2) per-image radix-select + bitonic sort (1 block/image) ----------------
__global__ void __launch_bounds__(1024) select_sort_kernel() {
    const int img = blockIdx.x;
    const unsigned* keys = d_keys + (size_t)img * NN;
    const int tid = threadIdx.x;
    const int lane = tid & 31, wid = tid >> 5;

    __shared__ unsigned hist[256];
    __shared__ unsigned sh_bucket, sh_need;
    __shared__ unsigned long long sh_sort[SORTN];
    __shared__ unsigned warpsum[32];
    __shared__ unsigned cursor, eqbase, chunk_total;

    if (tid == 0) sh_need = PRE;
    __syncthreads();

    unsigned prefix = 0, pmask = 0;
    for (int round = 0; round < 4; round++) {
        int shift = 24 - 8 * round;
        if (tid < 256) hist[tid] = 0;
        __syncthreads();
        for (int i = tid; i < NN; i += blockDim.x) {
            unsigned k = keys[i];
            if ((k & pmask) == prefix) atomicAdd(&hist[(k >> shift) & 255u], 1u);
        }
        __syncthreads();
        if (tid == 0) {
            unsigned nd = sh_need;
            unsigned cum = 0;
            int bsel = 0;
            for (int v = 255; v >= 0; v--) {
                if (cum + hist[v] >= nd) { bsel = v; break; }
                cum += hist[v];
            }
            sh_bucket = (unsigned)bsel;
            sh_need = nd - cum;
        }
        __syncthreads();
        prefix |= (sh_bucket << shift);
        pmask  |= (0xFFu << shift);
        __syncthreads();
    }
    const unsigned T = prefix;
    const unsigned need_eq = sh_need;

    // ---- ordered compaction: all keys > T, plus first need_eq keys == T by index ----
    if (tid == 0) { cursor = 0; eqbase = 0; }
    for (int i = tid; i < SORTN; i += blockDim.x)
        sh_sort[i] = 0xFFFFFFFFFFFFFFFFull;   // pad sorts to the end (ascending)
    __syncthreads();

    for (int base = 0; base < NN; base += blockDim.x) {
        int i = base + tid;
        unsigned k = (i < NN) ? keys[i] : 0u;
        unsigned isgt = (i < NN && k > T) ? 1u : 0u;
        unsigned iseq = (i < NN && k == T) ? 1u : 0u;

        // block exclusive scan of iseq
        unsigned v = iseq;
        #pragma unroll
        for (int off = 1; off < 32; off <<= 1) {
            unsigned tmp = __shfl_up_sync(0xffffffffu, v, off);
            if (lane >= off) v += tmp;
        }
        if (lane == 31) warpsum[wid] = v;
        __syncthreads();
        if (wid == 0) {
            unsigned wv = warpsum[lane];
            unsigned vv = wv;
            #pragma unroll
            for (int off = 1; off < 32; off <<= 1) {
                unsigned tmp = __shfl_up_sync(0xffffffffu, vv, off);
                if (lane >= off) vv += tmp;
            }
            warpsum[lane] = vv - wv;            // exclusive warp base
            if (lane == 31) chunk_total = vv;   // total eq in chunk
        }
        __syncthreads();
        unsigned excl = v - iseq + warpsum[wid];
        unsigned eqrank = eqbase + excl;
        bool take = isgt || (iseq && eqrank < need_eq);
        if (take) {
            unsigned pos = atomicAdd(&cursor, 1u);
            sh_sort[pos] = (((unsigned long long)(~k)) << 32) | (unsigned)i;
        }
        __syncthreads();
        if (tid == 0) eqbase += chunk_total;
        __syncthreads();
    }

    // ---- bitonic sort ascending on (~key, idx): == key desc, idx asc (top_k order) ----
    for (unsigned size = 2; size <= SORTN; size <<= 1) {
        for (unsigned stride = size >> 1; stride > 0; stride >>= 1) {
            __syncthreads();
            for (int t = tid; t < SORTN; t += blockDim.x) {
                int l = t ^ (int)stride;
                if (l > t) {
                    unsigned long long a = sh_sort[t], b = sh_sort[l];
                    bool asc = ((t & size) == 0);
                    if ((a > b) == asc) { sh_sort[t] = b; sh_sort[l] = a; }
                }
            }
        }
    }
    __syncthreads();

    // ---- gather boxes in sorted order ----
    const float4* props = d_props + (size_t)img * NN;
    float4* sorted = d_sorted + (size_t)img * PRE;
    for (int r = tid; r < PRE; r += blockDim.x) {
        unsigned idx = (unsigned)(sh_sort[r] & 0xFFFFFFFFull);
        sorted[r] = props[idx];
    }
}

// ---------------- 3) batched greedy NMS (1 block/image), early exit at 300 kept ----------------
__global__ void __launch_bounds__(512) nms_kernel(float* __restrict__ out) {
    const int img = blockIdx.x;
    const float4* boxes = d_sorted + (size_t)img * PRE;
    const int tid = threadIdx.x;

    __shared__ float4 kbox[POST];
    __shared__ float  karea[POST];
    __shared__ float4 cbox[32];
    __shared__ float  carea[32];
    __shared__ int    flags[32];
    __shared__ int    kept_sh;

    if (tid == 0) kept_sh = 0;
    __syncthreads();
    int kept = 0;

    for (int base = 0; base < PRE; base += 32) {
        if (tid < 32) {
            float4 bx = boxes[base + tid];
            cbox[tid]  = bx;
            carea[tid] = areaf(bx);
            flags[tid] = 0;
        }
        __syncthreads();

        // phase 1: candidates vs existing kept list (parallel)
        for (int p = tid; p < 32 * kept; p += blockDim.x) {
            int c = p & 31, ki = p >> 5;
            if (iou_gt(cbox[c], carea[c], kbox[ki], karea[ki])) flags[c] = 1;
        }
        __syncthreads();

        // phase 2: intra-batch greedy in warp 0
        if (tid < 32) {
            const int l = tid;
            float4 mine = cbox[l];
            float  marea = carea[l];
            unsigned supdyn = 0;
            int kl = kept;
            for (int c = 0; c < 32; c++) {
                if (kl >= POST) break;
                if (flags[c] || ((supdyn >> c) & 1u)) continue;   // uniform across warp
                float4 cc = cbox[c];
                float  ca = carea[c];
                bool s = (l > c) && iou_gt(cc, ca, mine, marea);
                supdyn |= __ballot_sync(0xffffffffu, s);
                if (l == 0) {
                    kbox[kl]  = cc;
                    karea[kl] = ca;
                    float* o = out + ((size_t)img * POST + kl) * 5;
                    o[1] = cc.x; o[2] = cc.y; o[3] = cc.z; o[4] = cc.w;
                }
                kl++;
            }
            if (l == 0) kept_sh = kl;
        }
        __syncthreads();
        kept = kept_sh;
        if (kept >= POST) break;
    }
}

// ---------------- launch ----------------
extern "C" void kernel_launch(void* const* d_in, const int* in_sizes, int n_in,
                              void* d_out, int out_size) {
    const float* scores  = (const float*)d_in[0];
    const float* deltas  = (const float*)d_in[1];
    const float* im_info = (const float*)d_in[2];
    const float* anchors = (const float*)d_in[3];
    float* out = (float*)d_out;

    int total = BB * NN;
    decode_kernel<<<(total + 255) / 256, 256>>>(scores, deltas, im_info, anchors, out);
    select_sort_kernel<<<BB, 1024>>>();
    nms_kernel<<<BB, 512>>>(out);
}

// round 2
// speedup vs baseline: 1.0086x; 1.0086x over previous
#include <cuda_runtime.h>
#include <cstdint>

#define BB 4
#define AA 9
#define HH 50
#define WW 76
#define NN (AA * HH * WW)          // 34200 boxes per image
#define PRE 4000
#define POST 300
#define SORTN 4096
#define NMS_THR 0.7f
#define BATCH 64

// ---------------- static scratch ----------------
__device__ float4   d_props[BB * NN];
__device__ unsigned d_keys [BB * NN];

// ---------------- helpers ----------------
__device__ __forceinline__ float areaf(float4 b) {
    return __fmul_rn(__fsub_rn(b.z, b.x), __fsub_rn(b.w, b.y));
}

__device__ __forceinline__ bool iou_gt(float4 a, float aA, float4 b, float aB) {
    float xx1 = fmaxf(a.x, b.x);
    float yy1 = fmaxf(a.y, b.y);
    float xx2 = fminf(a.z, b.z);
    float yy2 = fminf(a.w, b.w);
    float w = fmaxf(__fsub_rn(xx2, xx1), 0.0f);
    float h = fmaxf(__fsub_rn(yy2, yy1), 0.0f);
    float inter = __fmul_rn(w, h);
    float denom = __fadd_rn(__fsub_rn(__fadd_rn(aA, aB), inter), 1e-9f);
    return __fdiv_rn(inter, denom) > NMS_THR;
}

// ---------------- 1) decode + key + output prefill ----------------
__global__ void decode_kernel(const float* __restrict__ scores,
                              const float* __restrict__ deltas,
                              const float* __restrict__ im_info,
                              const float* __restrict__ anchors,
                              float* __restrict__ out) {
    int t = blockIdx.x * blockDim.x + threadIdx.x;

    if (t < BB * POST * 5) {
        int col = t % 5;
        int b = t / (POST * 5);
        out[t] = (col == 0) ? (float)b : 0.0f;
    }
    if (t >= BB * NN) return;

    int b = t / NN;
    int i = t - b * NN;
    int a = i % AA;
    int p = i / AA;
    int x = p % WW;
    int y = p / WW;

    float sx = (float)(x * 16);
    float sy = (float)(y * 16);
    float ax1 = __fadd_rn(anchors[a * 4 + 0], sx);
    float ay1 = __fadd_rn(anchors[a * 4 + 1], sy);
    float ax2 = __fadd_rn(anchors[a * 4 + 2], sx);
    float ay2 = __fadd_rn(anchors[a * 4 + 3], sy);

    float w  = __fadd_rn(__fsub_rn(ax2, ax1), 1.0f);
    float h  = __fadd_rn(__fsub_rn(ay2, ay1), 1.0f);
    float cx = __fadd_rn(ax1, __fmul_rn(0.5f, w));
    float cy = __fadd_rn(ay1, __fmul_rn(0.5f, h));

    const int HW = HH * WW;
    size_t dbase = ((size_t)b * 4 * AA + a * 4) * HW + (size_t)y * WW + x;
    float dx  = deltas[dbase];
    float dy  = deltas[dbase + HW];
    float dz  = deltas[dbase + 2 * HW];
    float dw_ = deltas[dbase + 3 * HW];

    float pcx = __fadd_rn(__fmul_rn(dx, w), cx);
    float pcy = __fadd_rn(__fmul_rn(dy, h), cy);
    float pw  = __fmul_rn(expf(dz),  w);
    float ph  = __fmul_rn(expf(dw_), h);

    float x1 = __fsub_rn(pcx, __fmul_rn(0.5f, pw));
    float y1 = __fsub_rn(pcy, __fmul_rn(0.5f, ph));
    float x2 = __fadd_rn(pcx, __fmul_rn(0.5f, pw));
    float y2 = __fadd_rn(pcy, __fmul_rn(0.5f, ph));

    float hiw = __fsub_rn(im_info[b * 3 + 1], 1.0f);
    float hih = __fsub_rn(im_info[b * 3 + 0], 1.0f);
    x1 = fminf(fmaxf(x1, 0.0f), hiw);
    y1 = fminf(fmaxf(y1, 0.0f), hih);
    x2 = fminf(fmaxf(x2, 0.0f), hiw);
    y2 = fminf(fmaxf(y2, 0.0f), hih);

    d_props[t] = make_float4(x1, y1, x2, y2);

    float s = scores[((size_t)b * AA + a) * HW + (size_t)y * WW + x];
    unsigned bits = __float_as_uint(s);
    d_keys[t] = (bits & 0x80000000u) ? ~bits : (bits | 0x80000000u);
}

// ---------------- shared-mem union: histogram, then NMS state ----------------
struct NmsState {
    float4 kbox[POST];
    float  karea[POST];
    float4 cbox[BATCH];
    float  carea[BATCH];
    int    flags[BATCH];
};
union SharedU {
    unsigned hist[2048];
    NmsState n;
};

// ---------------- 2) fused: radix-select + bitonic sort + greedy NMS ----------------
__global__ void __launch_bounds__(1024) fused_kernel(float* __restrict__ out) {
    const int img = blockIdx.x;
    const unsigned* keys = d_keys + (size_t)img * NN;
    const int tid = threadIdx.x;
    const int lane = tid & 31, wid = tid >> 5;

    __shared__ unsigned long long sh_sort[SORTN];
    __shared__ SharedU u;
    __shared__ unsigned csum[64];
    __shared__ unsigned warpsum[32];
    __shared__ unsigned sh_bucket, sh_need, cursor, eqbase, chunk_total;
    __shared__ int kept_sh;

    if (tid == 0) sh_need = PRE;

    // ---- 3-round radix select: 11 / 11 / 10 bits ----
    unsigned prefix = 0, pmask = 0;
    const int shifts[3]  = {21, 10, 0};
    const int nbins3[3]  = {2048, 2048, 1024};
    for (int r = 0; r < 3; r++) {
        const int shift = shifts[r];
        const unsigned bmask = (unsigned)nbins3[r] - 1u;
        for (int i = tid; i < 2048; i += 1024) u.hist[i] = 0;
        __syncthreads();
        for (int i = tid; i < NN; i += 1024) {
            unsigned k = keys[i];
            if ((k & pmask) == prefix) atomicAdd(&u.hist[(k >> shift) & bmask], 1u);
        }
        __syncthreads();
        const int nch = nbins3[r] >> 5;
        if (tid < nch) {
            unsigned s = 0;
            for (int v = 0; v < 32; v++) s += u.hist[tid * 32 + v];
            csum[tid] = s;
        }
        __syncthreads();
        if (tid == 0) {
            unsigned nd = sh_need, cum = 0;
            int ch = nch - 1;
            for (; ch > 0; ch--) {
                if (cum + csum[ch] >= nd) break;
                cum += csum[ch];
            }
            int bsel = ch * 32;
            for (int v = ch * 32 + 31; v >= ch * 32; v--) {
                if (cum + u.hist[v] >= nd) { bsel = v; break; }
                cum += u.hist[v];
            }
            sh_bucket = (unsigned)bsel;
            sh_need = nd - cum;
        }
        __syncthreads();
        prefix |= (sh_bucket << shift);
        pmask  |= (bmask << shift);
        __syncthreads();
    }
    const unsigned T = prefix;
    const unsigned need_eq = sh_need;

    // ---- ordered compaction: keys > T, plus first need_eq keys == T by index ----
    if (tid == 0) { cursor = 0; eqbase = 0; }
    for (int i = tid; i < SORTN; i += 1024)
        sh_sort[i] = 0xFFFFFFFFFFFFFFFFull;
    __syncthreads();

    for (int base = 0; base < NN; base += 1024) {
        int i = base + tid;
        unsigned k = (i < NN) ? keys[i] : 0u;
        unsigned isgt = (i < NN && k > T) ? 1u : 0u;
        unsigned iseq = (i < NN && k == T) ? 1u : 0u;

        unsigned v = iseq;
        #pragma unroll
        for (int off = 1; off < 32; off <<= 1) {
            unsigned tmp = __shfl_up_sync(0xffffffffu, v, off);
            if (lane >= off) v += tmp;
        }
        if (lane == 31) warpsum[wid] = v;
        __syncthreads();
        if (wid == 0) {
            unsigned wv = warpsum[lane];
            unsigned vv = wv;
            #pragma unroll
            for (int off = 1; off < 32; off <<= 1) {
                unsigned tmp = __shfl_up_sync(0xffffffffu, vv, off);
                if (lane >= off) vv += tmp;
            }
            warpsum[lane] = vv - wv;
            if (lane == 31) chunk_total = vv;
        }
        __syncthreads();
        unsigned excl = v - iseq + warpsum[wid];
        unsigned eqrank = eqbase + excl;
        bool take = isgt || (iseq && eqrank < need_eq);
        if (take) {
            unsigned pos = atomicAdd(&cursor, 1u);
            sh_sort[pos] = (((unsigned long long)(~k)) << 32) | (unsigned)i;
        }
        __syncthreads();
        if (tid == 0) eqbase += chunk_total;
        __syncthreads();
    }

    // ---- bitonic sort ascending on (~key, idx): key desc, idx asc ----
    unsigned prev_stride = 0xFFFFu;
    for (unsigned size = 2; size <= SORTN; size <<= 1) {
        for (unsigned stride = size >> 1; stride > 0; stride >>= 1) {
            if (stride >= 32 || prev_stride >= 32) __syncthreads();
            else __syncwarp();
            for (int t = tid; t < SORTN; t += 1024) {
                int l = t ^ (int)stride;
                if (l > t) {
                    unsigned long long a = sh_sort[t], b = sh_sort[l];
                    bool asc = ((t & (int)size) == 0);
                    if ((a > b) == asc) { sh_sort[t] = b; sh_sort[l] = a; }
                }
            }
            prev_stride = stride;
        }
    }

    // ---- batched greedy NMS, early exit at 300 kept ----
    if (tid == 0) kept_sh = 0;
    __syncthreads();
    int kept = 0;
    const float4* props = d_props + (size_t)img * NN;

    for (int base = 0; base < PRE; base += BATCH) {
        if (tid < BATCH) {
            int ci = base + tid;
            if (ci < PRE) {
                unsigned idx = (unsigned)(sh_sort[ci] & 0xFFFFFFFFull);
                float4 bx = props[idx];
                u.n.cbox[tid]  = bx;
                u.n.carea[tid] = areaf(bx);
                u.n.flags[tid] = 0;
            } else {
                u.n.cbox[tid]  = make_float4(0.f, 0.f, 0.f, 0.f);
                u.n.carea[tid] = 0.f;
                u.n.flags[tid] = 1;   // never keep padding
            }
        }
        __syncthreads();

        // phase 1: candidates vs existing kept list (fully parallel)
        for (int p = tid; p < BATCH * kept; p += 1024) {
            int c = p & (BATCH - 1), ki = p >> 6;
            if (iou_gt(u.n.cbox[c], u.n.carea[c], u.n.kbox[ki], u.n.karea[ki]))
                u.n.flags[c] = 1;
        }
        __syncthreads();

        // phase 2: intra-batch greedy in warp 0, ffs over 64-bit alive mask
        if (tid < 32) {
            const int l = tid;
            float4 b0 = u.n.cbox[l],      b1 = u.n.cbox[l + 32];
            float  a0 = u.n.carea[l],     a1 = u.n.carea[l + 32];
            unsigned f0 = __ballot_sync(0xffffffffu, u.n.flags[l] != 0);
            unsigned f1 = __ballot_sync(0xffffffffu, u.n.flags[l + 32] != 0);
            unsigned long long rem = ~(((unsigned long long)f1 << 32) | (unsigned long long)f0);
            int kl = kept;
            while (rem && kl < POST) {
                int c = __ffsll((long long)rem) - 1;
                rem &= rem - 1;
                float4 cc = u.n.cbox[c];
                float  ca = u.n.carea[c];
                if (l == 0) {
                    u.n.kbox[kl]  = cc;
                    u.n.karea[kl] = ca;
                    float* o = out + ((size_t)img * POST + kl) * 5;
                    o[1] = cc.x; o[2] = cc.y; o[3] = cc.z; o[4] = cc.w;
                }
                kl++;
                bool s0 = (l > c)        && iou_gt(cc, ca, b0, a0);
                bool s1 = ((l + 32) > c) && iou_gt(cc, ca, b1, a1);
                unsigned m0 = __ballot_sync(0xffffffffu, s0);
                unsigned m1 = __ballot_sync(0xffffffffu, s1);
                rem &= ~(((unsigned long long)m1 << 32) | (unsigned long long)m0);
            }
            if (l == 0) kept_sh = kl;
        }
        __syncthreads();
        kept = kept_sh;
        if (kept >= POST) break;
    }
}

// ---------------- launch ----------------
extern "C" void kernel_launch(void* const* d_in, const int* in_sizes, int n_in,
                              void* d_out, int out_size) {
    const float* scores  = (const float*)d_in[0];
    const float* deltas  = (const float*)d_in[1];
    const float* im_info = (const float*)d_in[2];
    const float* anchors = (const float*)d_in[3];
    float* out = (float*)d_out;

    int total = BB * NN;
    decode_kernel<<<(total + 255) / 256, 256>>>(scores, deltas, im_info, anchors, out);
    fused_kernel<<<BB, 1024>>>(out);
}

// round 3
// speedup vs baseline: 1.4958x; 1.4831x over previous
#include <cuda_runtime.h>
#include <cstdint>

#define BB 4
#define AA 9
#define HH 50
#define WW 76
#define NN (AA * HH * WW)          // 34200 boxes per image
#define PRE 4000
#define POST 300
#define SORTN 4096                 // slow path sort size
#define FASTN 2048                 // fast path sort size
#define NMS_THR 0.7f

// ---------------- static scratch ----------------
__device__ float4   d_props[BB * NN];
__device__ unsigned d_keys [BB * NN];
__device__ int      d_slow [BB];

// ---------------- helpers ----------------
__device__ __forceinline__ float areaf(float4 b) {
    return __fmul_rn(__fsub_rn(b.z, b.x), __fsub_rn(b.w, b.y));
}

__device__ __forceinline__ bool iou_gt(float4 a, float aA, float4 b, float aB) {
    float xx1 = fmaxf(a.x, b.x);
    float yy1 = fmaxf(a.y, b.y);
    float xx2 = fminf(a.z, b.z);
    float yy2 = fminf(a.w, b.w);
    float w = fmaxf(__fsub_rn(xx2, xx1), 0.0f);
    float h = fmaxf(__fsub_rn(yy2, yy1), 0.0f);
    float inter = __fmul_rn(w, h);
    float denom = __fadd_rn(__fsub_rn(__fadd_rn(aA, aB), inter), 1e-9f);
    return __fdiv_rn(inter, denom) > NMS_THR;
}

// ---------------- 1) decode + key + output prefill ----------------
__global__ void decode_kernel(const float* __restrict__ scores,
                              const float* __restrict__ deltas,
                              const float* __restrict__ im_info,
                              const float* __restrict__ anchors,
                              float* __restrict__ out) {
    int t = blockIdx.x * blockDim.x + threadIdx.x;

    if (t < BB * POST * 5) {
        int col = t % 5;
        int b = t / (POST * 5);
        out[t] = (col == 0) ? (float)b : 0.0f;
    }
    if (t >= BB * NN) return;

    int b = t / NN;
    int i = t - b * NN;
    int a = i % AA;
    int p = i / AA;
    int x = p % WW;
    int y = p / WW;

    float sx = (float)(x * 16);
    float sy = (float)(y * 16);
    float ax1 = __fadd_rn(anchors[a * 4 + 0], sx);
    float ay1 = __fadd_rn(anchors[a * 4 + 1], sy);
    float ax2 = __fadd_rn(anchors[a * 4 + 2], sx);
    float ay2 = __fadd_rn(anchors[a * 4 + 3], sy);

    float w  = __fadd_rn(__fsub_rn(ax2, ax1), 1.0f);
    float h  = __fadd_rn(__fsub_rn(ay2, ay1), 1.0f);
    float cx = __fadd_rn(ax1, __fmul_rn(0.5f, w));
    float cy = __fadd_rn(ay1, __fmul_rn(0.5f, h));

    const int HW = HH * WW;
    size_t dbase = ((size_t)b * 4 * AA + a * 4) * HW + (size_t)y * WW + x;
    float dx  = deltas[dbase];
    float dy  = deltas[dbase + HW];
    float dz  = deltas[dbase + 2 * HW];
    float dw_ = deltas[dbase + 3 * HW];

    float pcx = __fadd_rn(__fmul_rn(dx, w), cx);
    float pcy = __fadd_rn(__fmul_rn(dy, h), cy);
    float pw  = __fmul_rn(expf(dz),  w);
    float ph  = __fmul_rn(expf(dw_), h);

    float x1 = __fsub_rn(pcx, __fmul_rn(0.5f, pw));
    float y1 = __fsub_rn(pcy, __fmul_rn(0.5f, ph));
    float x2 = __fadd_rn(pcx, __fmul_rn(0.5f, pw));
    float y2 = __fadd_rn(pcy, __fmul_rn(0.5f, ph));

    float hiw = __fsub_rn(im_info[b * 3 + 1], 1.0f);
    float hih = __fsub_rn(im_info[b * 3 + 0], 1.0f);
    x1 = fminf(fmaxf(x1, 0.0f), hiw);
    y1 = fminf(fmaxf(y1, 0.0f), hih);
    x2 = fminf(fmaxf(x2, 0.0f), hiw);
    y2 = fminf(fmaxf(y2, 0.0f), hih);

    d_props[t] = make_float4(x1, y1, x2, y2);

    float s = scores[((size_t)b * AA + a) * HW + (size_t)y * WW + x];
    unsigned bits = __float_as_uint(s);
    d_keys[t] = (bits & 0x80000000u) ? ~bits : (bits | 0x80000000u);
}

// ---------------- shared-mem NMS state ----------------
struct NmsState32 {
    float4 kbox[POST];
    float  karea[POST];
    float4 cbox[32];
    float  carea[32];
    int    flags[32];
};
struct NmsState64 {
    float4 kbox[POST];
    float  karea[POST];
    float4 cbox[64];
    float  carea[64];
    int    flags[64];
};
union SharedFast { unsigned hist[2048]; NmsState32 n; };
union SharedSlow { unsigned hist[2048]; NmsState64 n; };

// ---------------- 2) FAST: rank-1024 prefix select + sort-2048 + NMS ----------------
__global__ void __launch_bounds__(1024) fast_kernel(float* __restrict__ out) {
    const int img = blockIdx.x;
    const unsigned* keys = d_keys + (size_t)img * NN;
    const int tid = threadIdx.x;

    __shared__ unsigned long long sh_sort[FASTN];
    __shared__ SharedFast u;
    __shared__ unsigned csum[64];
    __shared__ unsigned sh_bucket, sh_need, cursor, sh_cnt;
    __shared__ int kept_sh;

    if (tid == 0) sh_need = 1024;

    // ---- 3-round radix select for rank-1024 threshold ----
    unsigned prefix = 0, pmask = 0;
    const int shifts[3]  = {21, 10, 0};
    const int nbins3[3]  = {2048, 2048, 1024};
    for (int r = 0; r < 3; r++) {
        const int shift = shifts[r];
        const unsigned bmask = (unsigned)nbins3[r] - 1u;
        for (int i = tid; i < 2048; i += 1024) u.hist[i] = 0;
        __syncthreads();
        for (int i = tid; i < NN; i += 1024) {
            unsigned k = keys[i];
            if ((k & pmask) == prefix) atomicAdd(&u.hist[(k >> shift) & bmask], 1u);
        }
        __syncthreads();
        const int nch = nbins3[r] >> 5;
        if (tid < nch) {
            unsigned s = 0;
            for (int v = 0; v < 32; v++) s += u.hist[tid * 32 + v];
            csum[tid] = s;
        }
        __syncthreads();
        if (tid == 0) {
            unsigned nd = sh_need, cum = 0;
            int ch = nch - 1;
            for (; ch > 0; ch--) {
                if (cum + csum[ch] >= nd) break;
                cum += csum[ch];
            }
            int bsel = ch * 32;
            for (int v = ch * 32 + 31; v >= ch * 32; v--) {
                if (cum + u.hist[v] >= nd) { bsel = v; break; }
                cum += u.hist[v];
            }
            sh_bucket = (unsigned)bsel;
            sh_need = nd - cum;
            if (r == 2) {
                // cnt = #{> T} + #{== T} = (1024 - need_eq) + hist[bsel]
                sh_cnt = (1024u - (nd - cum)) + u.hist[bsel];
            }
        }
        __syncthreads();
        prefix |= (sh_bucket << shift);
        pmask  |= (bmask << shift);
        __syncthreads();
    }
    const unsigned T = prefix;
    const unsigned cnt = sh_cnt;

    if (cnt > FASTN) {              // tie-block overflow -> slow path
        if (tid == 0) d_slow[img] = 1;
        return;
    }

    // ---- unordered compaction: every key >= T (sort restores exact order) ----
    if (tid == 0) cursor = 0;
    for (int i = tid; i < FASTN; i += 1024)
        sh_sort[i] = 0xFFFFFFFFFFFFFFFFull;
    __syncthreads();
    for (int i = tid; i < NN; i += 1024) {
        unsigned k = keys[i];
        if (k >= T) {
            unsigned pos = atomicAdd(&cursor, 1u);
            sh_sort[pos] = (((unsigned long long)(~k)) << 32) | (unsigned)i;
        }
    }
    __syncthreads();

    // ---- bitonic sort ascending on (~key, idx): key desc, idx asc ----
    unsigned prev_stride = 0xFFFFu;
    for (unsigned size = 2; size <= FASTN; size <<= 1) {
        for (unsigned stride = size >> 1; stride > 0; stride >>= 1) {
            if (stride >= 32 || prev_stride >= 32) __syncthreads();
            else __syncwarp();
            #pragma unroll
            for (int rep = 0; rep < FASTN / 1024; rep++) {
                int t = tid + rep * 1024;
                int l = t ^ (int)stride;
                if (l > t) {
                    unsigned long long a = sh_sort[t], b = sh_sort[l];
                    bool asc = ((t & (int)size) == 0);
                    if ((a > b) == asc) { sh_sort[t] = b; sh_sort[l] = a; }
                }
            }
            prev_stride = stride;
        }
    }

    // ---- batched greedy NMS over the sorted prefix (batch 32) ----
    if (tid == 0) kept_sh = 0;
    __syncthreads();
    int kept = 0;
    const float4* props = d_props + (size_t)img * NN;

    for (int base = 0; base < (int)cnt && kept < POST; base += 32) {
        if (tid < 32) {
            int ci = base + tid;
            if (ci < (int)cnt) {
                unsigned idx = (unsigned)(sh_sort[ci] & 0xFFFFFFFFull);
                float4 bx = props[idx];
                u.n.cbox[tid]  = bx;
                u.n.carea[tid] = areaf(bx);
                u.n.flags[tid] = 0;
            } else {
                u.n.cbox[tid]  = make_float4(0.f, 0.f, 0.f, 0.f);
                u.n.carea[tid] = 0.f;
                u.n.flags[tid] = 1;
            }
        }
        __syncthreads();

        // phase 1: candidates vs kept list, fully parallel
        for (int p = tid; p < 32 * kept; p += 1024) {
            int c = p & 31, ki = p >> 5;
            if (iou_gt(u.n.cbox[c], u.n.carea[c], u.n.kbox[ki], u.n.karea[ki]))
                u.n.flags[c] = 1;
        }
        __syncthreads();

        // phase 2: intra-batch greedy in warp 0 (1 iou + 1 ballot per keep)
        if (tid < 32) {
            const int l = tid;
            float4 mine = u.n.cbox[l];
            float  marea = u.n.carea[l];
            unsigned rem = ~__ballot_sync(0xffffffffu, u.n.flags[l] != 0);
            int kl = kept;
            while (rem && kl < POST) {
                int c = __ffs((int)rem) - 1;
                rem &= rem - 1;
                float4 cc = u.n.cbox[c];
                float  ca = u.n.carea[c];
                if (l == 0) {
                    u.n.kbox[kl]  = cc;
                    u.n.karea[kl] = ca;
                    float* o = out + ((size_t)img * POST + kl) * 5;
                    o[1] = cc.x; o[2] = cc.y; o[3] = cc.z; o[4] = cc.w;
                }
                kl++;
                bool s = (l > c) && iou_gt(cc, ca, mine, marea);
                rem &= ~__ballot_sync(0xffffffffu, s);
            }
            if (l == 0) kept_sh = kl;
        }
        __syncthreads();
        kept = kept_sh;
    }

    if (tid == 0) d_slow[img] = (kept < POST) ? 1 : 0;
}

// ---------------- 3) SLOW fallback: full select-4000 + sort-4096 + NMS ----------------
__global__ void __launch_bounds__(1024) slow_kernel(float* __restrict__ out) {
    const int img = blockIdx.x;
    if (d_slow[img] == 0) return;

    const unsigned* keys = d_keys + (size_t)img * NN;
    const int tid = threadIdx.x;
    const int lane = tid & 31, wid = tid >> 5;

    __shared__ unsigned long long sh_sort[SORTN];
    __shared__ SharedSlow u;
    __shared__ unsigned csum[64];
    __shared__ unsigned warpsum[32];
    __shared__ unsigned sh_bucket, sh_need, cursor, eqbase, chunk_total;
    __shared__ int kept_sh;

    if (tid == 0) sh_need = PRE;

    unsigned prefix = 0, pmask = 0;
    const int shifts[3]  = {21, 10, 0};
    const int nbins3[3]  = {2048, 2048, 1024};
    for (int r = 0; r < 3; r++) {
        const int shift = shifts[r];
        const unsigned bmask = (unsigned)nbins3[r] - 1u;
        for (int i = tid; i < 2048; i += 1024) u.hist[i] = 0;
        __syncthreads();
        for (int i = tid; i < NN; i += 1024) {
            unsigned k = keys[i];
            if ((k & pmask) == prefix) atomicAdd(&u.hist[(k >> shift) & bmask], 1u);
        }
        __syncthreads();
        const int nch = nbins3[r] >> 5;
        if (tid < nch) {
            unsigned s = 0;
            for (int v = 0; v < 32; v++) s += u.hist[tid * 32 + v];
            csum[tid] = s;
        }
        __syncthreads();
        if (tid == 0) {
            unsigned nd = sh_need, cum = 0;
            int ch = nch - 1;
            for (; ch > 0; ch--) {
                if (cum + csum[ch] >= nd) break;
                cum += csum[ch];
            }
            int bsel = ch * 32;
            for (int v = ch * 32 + 31; v >= ch * 32; v--) {
                if (cum + u.hist[v] >= nd) { bsel = v; break; }
                cum += u.hist[v];
            }
            sh_bucket = (unsigned)bsel;
            sh_need = nd - cum;
        }
        __syncthreads();
        prefix |= (sh_bucket << shift);
        pmask  |= (bmask << shift);
        __syncthreads();
    }
    const unsigned T = prefix;
    const unsigned need_eq = sh_need;

    // ordered compaction: keys > T, plus first need_eq keys == T by index
    if (tid == 0) { cursor = 0; eqbase = 0; }
    for (int i = tid; i < SORTN; i += 1024)
        sh_sort[i] = 0xFFFFFFFFFFFFFFFFull;
    __syncthreads();

    for (int base = 0; base < NN; base += 1024) {
        int i = base + tid;
        unsigned k = (i < NN) ? keys[i] : 0u;
        unsigned isgt = (i < NN && k > T) ? 1u : 0u;
        unsigned iseq = (i < NN && k == T) ? 1u : 0u;

        unsigned v = iseq;
        #pragma unroll
        for (int off = 1; off < 32; off <<= 1) {
            unsigned tmp = __shfl_up_sync(0xffffffffu, v, off);
            if (lane >= off) v += tmp;
        }
        if (lane == 31) warpsum[wid] = v;
        __syncthreads();
        if (wid == 0) {
            unsigned wv = warpsum[lane];
            unsigned vv = wv;
            #pragma unroll
            for (int off = 1; off < 32; off <<= 1) {
                unsigned tmp = __shfl_up_sync(0xffffffffu, vv, off);
                if (lane >= off) vv += tmp;
            }
            warpsum[lane] = vv - wv;
            if (lane == 31) chunk_total = vv;
        }
        __syncthreads();
        unsigned excl = v - iseq + warpsum[wid];
        unsigned eqrank = eqbase + excl;
        bool take = isgt || (iseq && eqrank < need_eq);
        if (take) {
            unsigned pos = atomicAdd(&cursor, 1u);
            sh_sort[pos] = (((unsigned long long)(~k)) << 32) | (unsigned)i;
        }
        __syncthreads();
        if (tid == 0) eqbase += chunk_total;
        __syncthreads();
    }

    unsigned prev_stride = 0xFFFFu;
    for (unsigned size = 2; size <= SORTN; size <<= 1) {
        for (unsigned stride = size >> 1; stride > 0; stride >>= 1) {
            if (stride >= 32 || prev_stride >= 32) __syncthreads();
            else __syncwarp();
            #pragma unroll
            for (int rep = 0; rep < SORTN / 1024; rep++) {
                int t = tid + rep * 1024;
                int l = t ^ (int)stride;
                if (l > t) {
                    unsigned long long a = sh_sort[t], b = sh_sort[l];
                    bool asc = ((t & (int)size) == 0);
                    if ((a > b) == asc) { sh_sort[t] = b; sh_sort[l] = a; }
                }
            }
            prev_stride = stride;
        }
    }

    if (tid == 0) kept_sh = 0;
    __syncthreads();
    int kept = 0;
    const float4* props = d_props + (size_t)img * NN;

    for (int base = 0; base < PRE; base += 64) {
        if (tid < 64) {
            int ci = base + tid;
            if (ci < PRE) {
                unsigned idx = (unsigned)(sh_sort[ci] & 0xFFFFFFFFull);
                float4 bx = props[idx];
                u.n.cbox[tid]  = bx;
                u.n.carea[tid] = areaf(bx);
                u.n.flags[tid] = 0;
            } else {
                u.n.cbox[tid]  = make_float4(0.f, 0.f, 0.f, 0.f);
                u.n.carea[tid] = 0.f;
                u.n.flags[tid] = 1;
            }
        }
        __syncthreads();

        for (int p = tid; p < 64 * kept; p += 1024) {
            int c = p & 63, ki = p >> 6;
            if (iou_gt(u.n.cbox[c], u.n.carea[c], u.n.kbox[ki], u.n.karea[ki]))
                u.n.flags[c] = 1;
        }
        __syncthreads();

        if (tid < 32) {
            const int l = tid;
            float4 b0 = u.n.cbox[l],      b1 = u.n.cbox[l + 32];
            float  a0 = u.n.carea[l],     a1 = u.n.carea[l + 32];
            unsigned f0 = __ballot_sync(0xffffffffu, u.n.flags[l] != 0);
            unsigned f1 = __ballot_sync(0xffffffffu, u.n.flags[l + 32] != 0);
            unsigned long long rem = ~(((unsigned long long)f1 << 32) | (unsigned long long)f0);
            int kl = kept;
            while (rem && kl < POST) {
                int c = __ffsll((long long)rem) - 1;
                rem &= rem - 1;
                float4 cc = u.n.cbox[c];
                float  ca = u.n.carea[c];
                if (l == 0) {
                    u.n.kbox[kl]  = cc;
                    u.n.karea[kl] = ca;
                    float* o = out + ((size_t)img * POST + kl) * 5;
                    o[1] = cc.x; o[2] = cc.y; o[3] = cc.z; o[4] = cc.w;
                }
                kl++;
                bool s0 = (l > c)        && iou_gt(cc, ca, b0, a0);
                bool s1 = ((l + 32) > c) && iou_gt(cc, ca, b1, a1);
                unsigned m0 = __ballot_sync(0xffffffffu, s0);
                unsigned m1 = __ballot_sync(0xffffffffu, s1);
                rem &= ~(((unsigned long long)m1 << 32) | (unsigned long long)m0);
            }
            if (l == 0) kept_sh = kl;
        }
        __syncthreads();
        kept = kept_sh;
        if (kept >= POST) break;
    }
}

// ---------------- launch ----------------
extern "C" void kernel_launch(void* const* d_in, const int* in_sizes, int n_in,
                              void* d_out, int out_size) {
    const float* scores  = (const float*)d_in[0];
    const float* deltas  = (const float*)d_in[1];
    const float* im_info = (const float*)d_in[2];
    const float* anchors = (const float*)d_in[3];
    float* out = (float*)d_out;

    int total = BB * NN;
    decode_kernel<<<(total + 255) / 256, 256>>>(scores, deltas, im_info, anchors, out);
    fast_kernel<<<BB, 1024>>>(out);
    slow_kernel<<<BB, 1024>>>(out);
}

// round 4
// speedup vs baseline: 2.3489x; 1.5703x over previous
#include <cuda_runtime.h>
#include <cstdint>

#define BB 4
#define AA 9
#define HH 50
#define WW 76
#define NN (AA * HH * WW)          // 34200 boxes per image
#define PRE 4000
#define POST 300
#define SORTN 4096                 // slow path sort size
#define FASTN 2048                 // fast path sort size
#define NMS_THR 0.7f
#define NBINS 2048

// ---------------- static scratch ----------------
__device__ float4   d_props[BB * NN];
__device__ unsigned d_keys [BB * NN];
__device__ unsigned d_hist [BB * NBINS];   // zero-init at load; fast_kernel re-zeroes each run
__device__ int      d_slow [BB];

// ---------------- helpers ----------------
__device__ __forceinline__ float areaf(float4 b) {
    return __fmul_rn(__fsub_rn(b.z, b.x), __fsub_rn(b.w, b.y));
}

__device__ __forceinline__ bool iou_gt(float4 a, float aA, float4 b, float aB) {
    float xx1 = fmaxf(a.x, b.x);
    float yy1 = fmaxf(a.y, b.y);
    float xx2 = fminf(a.z, b.z);
    float yy2 = fminf(a.w, b.w);
    float w = fmaxf(__fsub_rn(xx2, xx1), 0.0f);
    float h = fmaxf(__fsub_rn(yy2, yy1), 0.0f);
    float inter = __fmul_rn(w, h);
    float denom = __fadd_rn(__fsub_rn(__fadd_rn(aA, aB), inter), 1e-9f);
    return __fdiv_rn(inter, denom) > NMS_THR;
}

// ---------------- 1) decode + key + histogram + output prefill ----------------
__global__ void decode_kernel(const float* __restrict__ scores,
                              const float* __restrict__ deltas,
                              const float* __restrict__ im_info,
                              const float* __restrict__ anchors,
                              float* __restrict__ out) {
    int t = blockIdx.x * blockDim.x + threadIdx.x;

    if (t < BB * POST * 5) {
        int col = t % 5;
        int b = t / (POST * 5);
        out[t] = (col == 0) ? (float)b : 0.0f;
    }
    if (t >= BB * NN) return;

    int b = t / NN;
    int i = t - b * NN;
    int a = i % AA;
    int p = i / AA;
    int x = p % WW;
    int y = p / WW;

    float sx = (float)(x * 16);
    float sy = (float)(y * 16);
    float ax1 = __fadd_rn(anchors[a * 4 + 0], sx);
    float ay1 = __fadd_rn(anchors[a * 4 + 1], sy);
    float ax2 = __fadd_rn(anchors[a * 4 + 2], sx);
    float ay2 = __fadd_rn(anchors[a * 4 + 3], sy);

    float w  = __fadd_rn(__fsub_rn(ax2, ax1), 1.0f);
    float h  = __fadd_rn(__fsub_rn(ay2, ay1), 1.0f);
    float cx = __fadd_rn(ax1, __fmul_rn(0.5f, w));
    float cy = __fadd_rn(ay1, __fmul_rn(0.5f, h));

    const int HW = HH * WW;
    size_t dbase = ((size_t)b * 4 * AA + a * 4) * HW + (size_t)y * WW + x;
    float dx  = deltas[dbase];
    float dy  = deltas[dbase + HW];
    float dz  = deltas[dbase + 2 * HW];
    float dw_ = deltas[dbase + 3 * HW];

    float pcx = __fadd_rn(__fmul_rn(dx, w), cx);
    float pcy = __fadd_rn(__fmul_rn(dy, h), cy);
    float pw  = __fmul_rn(expf(dz),  w);
    float ph  = __fmul_rn(expf(dw_), h);

    float x1 = __fsub_rn(pcx, __fmul_rn(0.5f, pw));
    float y1 = __fsub_rn(pcy, __fmul_rn(0.5f, ph));
    float x2 = __fadd_rn(pcx, __fmul_rn(0.5f, pw));
    float y2 = __fadd_rn(pcy, __fmul_rn(0.5f, ph));

    float hiw = __fsub_rn(im_info[b * 3 + 1], 1.0f);
    float hih = __fsub_rn(im_info[b * 3 + 0], 1.0f);
    x1 = fminf(fmaxf(x1, 0.0f), hiw);
    y1 = fminf(fmaxf(y1, 0.0f), hih);
    x2 = fminf(fmaxf(x2, 0.0f), hiw);
    y2 = fminf(fmaxf(y2, 0.0f), hih);

    d_props[t] = make_float4(x1, y1, x2, y2);

    float s = scores[((size_t)b * AA + a) * HW + (size_t)y * WW + x];
    unsigned bits = __float_as_uint(s);
    unsigned key = (bits & 0x80000000u) ? ~bits : (bits | 0x80000000u);
    d_keys[t] = key;
    atomicAdd(&d_hist[b * NBINS + (key >> 21)], 1u);
}

// ---------------- shared-mem NMS state (fast path) ----------------
struct NmsStateF {
    float4 kbox[POST];
    float  karea[POST];
    float4 cbox[64];
    float  carea[64];
    unsigned mlo[64];      // suppression matrix row, bits 0..31
    unsigned mhi[64];      // bits 32..63
    int    flags[64];
};
struct NmsState64 {
    float4 kbox[POST];
    float  karea[POST];
    float4 cbox[64];
    float  carea[64];
    int    flags[64];
};
union SharedFast { unsigned hist[NBINS]; NmsStateF n; };
union SharedSlow { unsigned hist[2048]; NmsState64 n; };

// ---------------- 2) FAST: coarse-threshold select + sort-2048 + matrix NMS ----------------
__global__ void __launch_bounds__(1024) fast_kernel(float* __restrict__ out) {
    const int img = blockIdx.x;
    const unsigned* keys = d_keys + (size_t)img * NN;
    const int tid = threadIdx.x;

    __shared__ unsigned long long sh_sort[FASTN];
    __shared__ SharedFast u;
    __shared__ unsigned csum[64];
    __shared__ unsigned cursor, sh_cnt, sh_T;
    __shared__ int kept_sh;

    // ---- read precomputed histogram, zero it for the next replay ----
    unsigned* ghist = d_hist + img * NBINS;
    #pragma unroll
    for (int rep = 0; rep < NBINS / 1024; rep++) {
        int i = tid + rep * 1024;
        u.hist[i] = ghist[i];
        ghist[i] = 0;
    }
    __syncthreads();
    if (tid < 64) {
        unsigned s = 0;
        #pragma unroll
        for (int v = 0; v < 32; v++) s += u.hist[tid * 32 + v];
        csum[tid] = s;
    }
    __syncthreads();
    if (tid == 0) {
        // walk buckets from top until cumulative >= 1024; take the whole bucket
        unsigned cum = 0;
        int ch = 63;
        for (; ch > 0; ch--) {
            if (cum + csum[ch] >= 1024u) break;
            cum += csum[ch];
        }
        int bsel = ch * 32;
        for (int v = ch * 32 + 31; v >= ch * 32; v--) {
            if (cum + u.hist[v] >= 1024u) { bsel = v; break; }
            cum += u.hist[v];
        }
        sh_T = (unsigned)bsel << 21;
        sh_cnt = cum + u.hist[bsel];
        cursor = 0;
        kept_sh = 0;
    }
    __syncthreads();
    const unsigned T = sh_T;
    const unsigned cnt = sh_cnt;

    if (cnt > FASTN) {              // upper set too large -> slow path
        if (tid == 0) d_slow[img] = 1;
        return;
    }

    // ---- unordered compaction of every key >= T (sort restores exact top_k order) ----
    #pragma unroll
    for (int rep = 0; rep < FASTN / 1024; rep++)
        sh_sort[tid + rep * 1024] = 0xFFFFFFFFFFFFFFFFull;
    __syncthreads();
    for (int i = tid; i < NN; i += 1024) {
        unsigned k = keys[i];
        if (k >= T) {
            unsigned pos = atomicAdd(&cursor, 1u);
            sh_sort[pos] = (((unsigned long long)(~k)) << 32) | (unsigned)i;
        }
    }
    __syncthreads();

    // ---- bitonic sort ascending on (~key, idx): key desc, idx asc ----
    unsigned prev_stride = 0xFFFFu;
    for (unsigned size = 2; size <= FASTN; size <<= 1) {
        for (unsigned stride = size >> 1; stride > 0; stride >>= 1) {
            if (stride >= 32 || prev_stride >= 32) __syncthreads();
            else __syncwarp();
            #pragma unroll
            for (int rep = 0; rep < FASTN / 1024; rep++) {
                int t = tid + rep * 1024;
                int l = t ^ (int)stride;
                if (l > t) {
                    unsigned long long a = sh_sort[t], b = sh_sort[l];
                    bool asc = ((t & (int)size) == 0);
                    if ((a > b) == asc) { sh_sort[t] = b; sh_sort[l] = a; }
                }
            }
            prev_stride = stride;
        }
    }
    __syncthreads();

    // ---- batched greedy NMS with precomputed 64x64 suppression matrix ----
    int kept = 0;
    const float4* props = d_props + (size_t)img * NN;

    for (int base = 0; base < (int)cnt && kept < POST; base += 64) {
        if (tid < 64) {
            int ci = base + tid;
            if (ci < (int)cnt) {
                unsigned idx = (unsigned)(sh_sort[ci] & 0xFFFFFFFFull);
                float4 bx = props[idx];
                u.n.cbox[tid]  = bx;
                u.n.carea[tid] = areaf(bx);
                u.n.flags[tid] = 0;
            } else {
                u.n.cbox[tid]  = make_float4(0.f, 0.f, 0.f, 0.f);
                u.n.carea[tid] = 0.f;
                u.n.flags[tid] = 1;
            }
            u.n.mlo[tid] = 0u;
            u.n.mhi[tid] = 0u;
        }
        __syncthreads();

        // phase 1: candidates vs kept list (parallel)
        for (int p = tid; p < 64 * kept; p += 1024) {
            int c = p & 63, ki = p >> 6;
            if (iou_gt(u.n.cbox[c], u.n.carea[c], u.n.kbox[ki], u.n.karea[ki]))
                u.n.flags[c] = 1;
        }
        // phase 1b: 64x64 pair suppression matrix (parallel, 4 pairs/thread)
        #pragma unroll
        for (int rep = 0; rep < 4; rep++) {
            int p = tid + rep * 1024;
            int r = p >> 6, c = p & 63;
            if (c > r &&
                iou_gt(u.n.cbox[r], u.n.carea[r], u.n.cbox[c], u.n.carea[c])) {
                if (c < 32) atomicOr(&u.n.mlo[r], 1u << c);
                else        atomicOr(&u.n.mhi[r], 1u << (c - 32));
            }
        }
        __syncthreads();

        // phase 2: serial greedy via bit masks (single thread, no ballots, no IoU)
        if (tid == 0) {
            unsigned long long rem = 0;
            #pragma unroll
            for (int c = 0; c < 64; c++)
                rem |= (unsigned long long)(u.n.flags[c] == 0) << c;
            int kl = kept;
            while (rem && kl < POST) {
                int c = __ffsll((long long)rem) - 1;
                float4 cc = u.n.cbox[c];
                u.n.kbox[kl]  = cc;
                u.n.karea[kl] = u.n.carea[c];
                float* o = out + ((size_t)img * POST + kl) * 5;
                o[1] = cc.x; o[2] = cc.y; o[3] = cc.z; o[4] = cc.w;
                kl++;
                unsigned long long sup =
                    ((unsigned long long)u.n.mhi[c] << 32) | u.n.mlo[c];
                rem &= ~sup;
                rem &= ~(1ull << c);
            }
            kept_sh = kl;
        }
        __syncthreads();
        kept = kept_sh;
    }

    if (tid == 0) d_slow[img] = (kept < POST) ? 1 : 0;
}

// ---------------- 3) SLOW fallback: full select-4000 + sort-4096 + NMS ----------------
__global__ void __launch_bounds__(1024) slow_kernel(float* __restrict__ out) {
    const int img = blockIdx.x;
    if (d_slow[img] == 0) return;

    const unsigned* keys = d_keys + (size_t)img * NN;
    const int tid = threadIdx.x;
    const int lane = tid & 31, wid = tid >> 5;

    __shared__ unsigned long long sh_sort[SORTN];
    __shared__ SharedSlow u;
    __shared__ unsigned csum[64];
    __shared__ unsigned warpsum[32];
    __shared__ unsigned sh_bucket, sh_need, cursor, eqbase, chunk_total;
    __shared__ int kept_sh;

    if (tid == 0) sh_need = PRE;

    unsigned prefix = 0, pmask = 0;
    const int shifts[3]  = {21, 10, 0};
    const int nbins3[3]  = {2048, 2048, 1024};
    for (int r = 0; r < 3; r++) {
        const int shift = shifts[r];
        const unsigned bmask = (unsigned)nbins3[r] - 1u;
        for (int i = tid; i < 2048; i += 1024) u.hist[i] = 0;
        __syncthreads();
        for (int i = tid; i < NN; i += 1024) {
            unsigned k = keys[i];
            if ((k & pmask) == prefix) atomicAdd(&u.hist[(k >> shift) & bmask], 1u);
        }
        __syncthreads();
        const int nch = nbins3[r] >> 5;
        if (tid < nch) {
            unsigned s = 0;
            for (int v = 0; v < 32; v++) s += u.hist[tid * 32 + v];
            csum[tid] = s;
        }
        __syncthreads();
        if (tid == 0) {
            unsigned nd = sh_need, cum = 0;
            int ch = nch - 1;
            for (; ch > 0; ch--) {
                if (cum + csum[ch] >= nd) break;
                cum += csum[ch];
            }
            int bsel = ch * 32;
            for (int v = ch * 32 + 31; v >= ch * 32; v--) {
                if (cum + u.hist[v] >= nd) { bsel = v; break; }
                cum += u.hist[v];
            }
            sh_bucket = (unsigned)bsel;
            sh_need = nd - cum;
        }
        __syncthreads();
        prefix |= (sh_bucket << shift);
        pmask  |= (bmask << shift);
        __syncthreads();
    }
    const unsigned T = prefix;
    const unsigned need_eq = sh_need;

    if (tid == 0) { cursor = 0; eqbase = 0; }
    for (int i = tid; i < SORTN; i += 1024)
        sh_sort[i] = 0xFFFFFFFFFFFFFFFFull;
    __syncthreads();

    for (int base = 0; base < NN; base += 1024) {
        int i = base + tid;
        unsigned k = (i < NN) ? keys[i] : 0u;
        unsigned isgt = (i < NN && k > T) ? 1u : 0u;
        unsigned iseq = (i < NN && k == T) ? 1u : 0u;

        unsigned v = iseq;
        #pragma unroll
        for (int off = 1; off < 32; off <<= 1) {
            unsigned tmp = __shfl_up_sync(0xffffffffu, v, off);
            if (lane >= off) v += tmp;
        }
        if (lane == 31) warpsum[wid] = v;
        __syncthreads();
        if (wid == 0) {
            unsigned wv = warpsum[lane];
            unsigned vv = wv;
            #pragma unroll
            for (int off = 1; off < 32; off <<= 1) {
                unsigned tmp = __shfl_up_sync(0xffffffffu, vv, off);
                if (lane >= off) vv += tmp;
            }
            warpsum[lane] = vv - wv;
            if (lane == 31) chunk_total = vv;
        }
        __syncthreads();
        unsigned excl = v - iseq + warpsum[wid];
        unsigned eqrank = eqbase + excl;
        bool take = isgt || (iseq && eqrank < need_eq);
        if (take) {
            unsigned pos = atomicAdd(&cursor, 1u);
            sh_sort[pos] = (((unsigned long long)(~k)) << 32) | (unsigned)i;
        }
        __syncthreads();
        if (tid == 0) eqbase += chunk_total;
        __syncthreads();
    }

    unsigned prev_stride = 0xFFFFu;
    for (unsigned size = 2; size <= SORTN; size <<= 1) {
        for (unsigned stride = size >> 1; stride > 0; stride >>= 1) {
            if (stride >= 32 || prev_stride >= 32) __syncthreads();
            else __syncwarp();
            #pragma unroll
            for (int rep = 0; rep < SORTN / 1024; rep++) {
                int t = tid + rep * 1024;
                int l = t ^ (int)stride;
                if (l > t) {
                    unsigned long long a = sh_sort[t], b = sh_sort[l];
                    bool asc = ((t & (int)size) == 0);
                    if ((a > b) == asc) { sh_sort[t] = b; sh_sort[l] = a; }
                }
            }
            prev_stride = stride;
        }
    }

    if (tid == 0) kept_sh = 0;
    __syncthreads();
    int kept = 0;
    const float4* props = d_props + (size_t)img * NN;

    for (int base = 0; base < PRE; base += 64) {
        if (tid < 64) {
            int ci = base + tid;
            if (ci < PRE) {
                unsigned idx = (unsigned)(sh_sort[ci] & 0xFFFFFFFFull);
                float4 bx = props[idx];
                u.n.cbox[tid]  = bx;
                u.n.carea[tid] = areaf(bx);
                u.n.flags[tid] = 0;
            } else {
                u.n.cbox[tid]  = make_float4(0.f, 0.f, 0.f, 0.f);
                u.n.carea[tid] = 0.f;
                u.n.flags[tid] = 1;
            }
        }
        __syncthreads();

        for (int p = tid; p < 64 * kept; p += 1024) {
            int c = p & 63, ki = p >> 6;
            if (iou_gt(u.n.cbox[c], u.n.carea[c], u.n.kbox[ki], u.n.karea[ki]))
                u.n.flags[c] = 1;
        }
        __syncthreads();

        if (tid < 32) {
            const int l = tid;
            float4 b0 = u.n.cbox[l],      b1 = u.n.cbox[l + 32];
            float  a0 = u.n.carea[l],     a1 = u.n.carea[l + 32];
            unsigned f0 = __ballot_sync(0xffffffffu, u.n.flags[l] != 0);
            unsigned f1 = __ballot_sync(0xffffffffu, u.n.flags[l + 32] != 0);
            unsigned long long rem = ~(((unsigned long long)f1 << 32) | (unsigned long long)f0);
            int kl = kept;
            while (rem && kl < POST) {
                int c = __ffsll((long long)rem) - 1;
                rem &= rem - 1;
                float4 cc = u.n.cbox[c];
                float  ca = u.n.carea[c];
                if (l == 0) {
                    u.n.kbox[kl]  = cc;
                    u.n.karea[kl] = ca;
                    float* o = out + ((size_t)img * POST + kl) * 5;
                    o[1] = cc.x; o[2] = cc.y; o[3] = cc.z; o[4] = cc.w;
                }
                kl++;
                bool s0 = (l > c)        && iou_gt(cc, ca, b0, a0);
                bool s1 = ((l + 32) > c) && iou_gt(cc, ca, b1, a1);
                unsigned m0 = __ballot_sync(0xffffffffu, s0);
                unsigned m1 = __ballot_sync(0xffffffffu, s1);
                rem &= ~(((unsigned long long)m1 << 32) | (unsigned long long)m0);
            }
            if (l == 0) kept_sh = kl;
        }
        __syncthreads();
        kept = kept_sh;
        if (kept >= POST) break;
    }
}

// ---------------- launch ----------------
extern "C" void kernel_launch(void* const* d_in, const int* in_sizes, int n_in,
                              void* d_out, int out_size) {
    const float* scores  = (const float*)d_in[0];
    const float* deltas  = (const float*)d_in[1];
    const float* im_info = (const float*)d_in[2];
    const float* anchors = (const float*)d_in[3];
    float* out = (float*)d_out;

    int total = BB * NN;
    decode_kernel<<<(total + 255) / 256, 256>>>(scores, deltas, im_info, anchors, out);
    fast_kernel<<<BB, 1024>>>(out);
    slow_kernel<<<BB, 1024>>>(out);
}